// round 12
// baseline (speedup 1.0000x reference)
#include <cuda_runtime.h>
#include <cstdint>

#define H_IMG 64
#define W_IMG 64
#define CH    128
#define HD    32
#define HEADS 4
#define KS    3
#define DIL   2
#define KK    9
#define PLANE 4096

#define TW 32                  // tile width (pixels)
#define TH 4                   // tile height
#define NTHREADS (TW*TH)       // 128, 1 pixel per thread

#define CPC 4                  // channels per stage
#define NST_K 8                // k stages
#define NST   16               // total stages
#define SH (TH + 4)            // 8 rows
#define SWP 40                 // padded cols: gx in [tileX-4, tileX+36)
#define SEGS 10                // float4 segments per row
#define CELLS (CPC*SH*SEGS)    // 320
#define STAGE_FLOATS (CPC*SH*SWP)   // 1280 (5 KB)
#define RING 4
#define RING_BYTES (STAGE_FLOATS*4) // 5120

__device__ __forceinline__ uint32_t s2u(const void* p) {
    return (uint32_t)__cvta_generic_to_shared(p);
}

#define CP_ASYNC(sa, gp, sz) \
    asm volatile("cp.async.cg.shared.global [%0], [%1], 16, %2;\n" \
                 :: "r"(sa), "l"(gp), "r"(sz) : "memory")
#define CP_COMMIT() asm volatile("cp.async.commit_group;\n" ::: "memory")
#define CP_WAIT2()  asm volatile("cp.async.wait_group 2;\n" ::: "memory")

__global__ __launch_bounds__(NTHREADS, 11)
void dilate_attn_kernel(const float* __restrict__ q,
                        const float* __restrict__ k,
                        const float* __restrict__ v,
                        float* __restrict__ out)
{
    __shared__ __align__(16) float ring[RING][STAGE_FLOATS];   // 20 KB

    const int tx  = threadIdx.x;              // 0..31
    const int ty  = threadIdx.y;              // 0..3
    const int tid = ty * TW + tx;

    const int tilesX = W_IMG / TW;            // 2
    const int tileX = (blockIdx.x % tilesX) * TW;
    const int tileY = (blockIdx.x / tilesX) * TH;
    const int head  = blockIdx.y;
    const int b     = blockIdx.z;

    const int x   = tileX + tx;
    const int y   = tileY + ty;
    const int pix = y * W_IMG + x;

    const float scale = 0.1767766952966369f;  // 32^-0.5

    const size_t base = ((size_t)b * CH + head * HD) * PLANE;
    const float* kb = k + base;
    const float* vb = v + base;
    const float* qb = q + base + pix;

    // ---- precompute staging descriptors (loop-invariant across stages) ----
    // cells: tid, tid+128, tid+256 (third valid iff tid < 64 -> warps 0,1)
    int  goff[3], gsz[3];
    uint32_t gsa[3];
    {
        const uint32_t sbase = s2u(&ring[0][0]);
#pragma unroll
        for (int cell = 0; cell < 3; cell++) {
            const int i   = tid + cell * NTHREADS;
            const int ch  = i / (SH * SEGS);
            const int rem = i - ch * (SH * SEGS);
            const int row = rem / SEGS;
            const int seg = rem - row * SEGS;
            const int gy  = tileY - 2 + row;
            const int gx  = tileX - 4 + seg * 4;
            const bool inb = (gy >= 0) & (gy < H_IMG) & (gx >= 0) & (gx < W_IMG);
            goff[cell] = inb ? (ch * PLANE + gy * W_IMG + gx) : 0;
            gsz[cell]  = inb ? 16 : 0;
            gsa[cell]  = sbase + (uint32_t)(ch * (SH * SWP) + row * SWP + seg * 4) * 4u;
        }
    }
    const bool cell2 = (tid < CELLS - 2 * NTHREADS);   // tid < 64

#define ISSUE(srcptr, r) do { \
        CP_ASYNC(gsa[0] + (r) * RING_BYTES, (srcptr) + goff[0], gsz[0]); \
        CP_ASYNC(gsa[1] + (r) * RING_BYTES, (srcptr) + goff[1], gsz[1]); \
        if (cell2) CP_ASYNC(gsa[2] + (r) * RING_BYTES, (srcptr) + goff[2], gsz[2]); \
        CP_COMMIT(); \
    } while (0)

    // ---- prologue: issue k stages 0,1,2 ----
    ISSUE(kb,               0);
    ISSUE(kb + 1*CPC*PLANE, 1);
    ISSUE(kb + 2*CPC*PLANE, 2);

    float qcur[CPC], qnxt[CPC];
#pragma unroll
    for (int c = 0; c < CPC; c++) qcur[c] = __ldg(qb + (size_t)c * PLANE);
#pragma unroll
    for (int c = 0; c < CPC; c++) qnxt[c] = __ldg(qb + (size_t)(CPC + c) * PLANE);

    float logit[KK];
#pragma unroll
    for (int i = 0; i < KK; i++) logit[i] = 0.f;

    // ================= q.k stages 0..7 =================
#pragma unroll
    for (int s = 0; s < NST_K; s++) {
        CP_WAIT2();
        __syncthreads();

        // issue stage s+3 (k stages 3..7, then v stages 0..2)
        {
            const int sn = s + 3;
            if (sn < NST_K) ISSUE(kb + sn * CPC * PLANE, sn % RING);
            else            ISSUE(vb + (sn - NST_K) * CPC * PLANE, sn % RING);
        }

        // compute stage s
        const float* tb = ring[s % RING];
#pragma unroll
        for (int c = 0; c < CPC; c++) {
            const float* tc = tb + c * (SH * SWP) + ty * SWP + tx + 2;
            const float qc = qcur[c];
#pragma unroll
            for (int ki = 0; ki < KS; ki++)
#pragma unroll
                for (int kj = 0; kj < KS; kj++)
                    logit[ki * KS + kj] = fmaf(qc, tc[(2 * ki) * SWP + 2 * kj],
                                               logit[ki * KS + kj]);
        }

        // rotate q prefetch (distance 2)
#pragma unroll
        for (int c = 0; c < CPC; c++) qcur[c] = qnxt[c];
        if (s + 2 < NST_K) {
#pragma unroll
            for (int c = 0; c < CPC; c++)
                qnxt[c] = __ldg(qb + (size_t)((s + 2) * CPC + c) * PLANE);
        }
    }

    // ================= softmax over 9 taps =================
    {
        float m = -1e30f;
#pragma unroll
        for (int i = 0; i < KK; i++) {
            logit[i] *= scale;
            m = fmaxf(m, logit[i]);
        }
        float ssum = 0.f;
#pragma unroll
        for (int i = 0; i < KK; i++) {
            logit[i] = __expf(logit[i] - m);
            ssum += logit[i];
        }
        const float inv = 1.f / ssum;
#pragma unroll
        for (int i = 0; i < KK; i++) logit[i] *= inv;   // logit[] = weights now
    }

    // ================= a.v stages 8..15 =================
    float* op = out + ((size_t)b * PLANE + pix) * CH + head * HD;

#pragma unroll
    for (int s = NST_K; s < NST; s++) {
        CP_WAIT2();
        __syncthreads();

        {
            const int sn = s + 3;
            if (sn < NST) ISSUE(vb + (sn - NST_K) * CPC * PLANE, sn % RING);
            else          CP_COMMIT();   // empty group: keeps drain count ahead
        }

        const float* tb = ring[s % RING];
        float o[CPC];
#pragma unroll
        for (int c = 0; c < CPC; c++) {
            const float* tc = tb + c * (SH * SWP) + ty * SWP + tx + 2;
            float acc = 0.f;
#pragma unroll
            for (int ki = 0; ki < KS; ki++)
#pragma unroll
                for (int kj = 0; kj < KS; kj++)
                    acc = fmaf(logit[ki * KS + kj], tc[(2 * ki) * SWP + 2 * kj], acc);
            o[c] = acc;
        }

        *reinterpret_cast<float4*>(op + (s - NST_K) * CPC) =
            make_float4(o[0], o[1], o[2], o[3]);
    }
#undef ISSUE
}

extern "C" void kernel_launch(void* const* d_in, const int* in_sizes, int n_in,
                              void* d_out, int out_size)
{
    const float* q = (const float*)d_in[0];
    const float* k = (const float*)d_in[1];
    const float* v = (const float*)d_in[2];
    float* out = (float*)d_out;

    dim3 block(TW, TH);
    dim3 grid((W_IMG / TW) * (H_IMG / TH), HEADS, 16 /*B*/);
    dilate_attn_kernel<<<grid, block>>>(q, k, v, out);
}

// round 14
// speedup vs baseline: 1.1366x; 1.1366x over previous
#include <cuda_runtime.h>
#include <cstdint>

#define H_IMG 64
#define W_IMG 64
#define CH    128
#define HD    32
#define HEADS 4
#define KS    3
#define DIL   2
#define KK    9
#define PLANE 4096

#define TW 32                  // tile width (pixels)
#define THP 8                  // tile height (pixels)
#define TYD 4                  // thread rows (2 px per thread, y-stride-2 pairs)
#define NTHREADS (TW*TYD)      // 128

#define CPC 4                  // channels per stage
#define NST_K 8                // k stages
#define NST   16               // total stages
#define SH (THP + 4)           // 12 smem rows
#define SWP 40                 // padded cols: gx in [tileX-4, tileX+36)
#define SEGS 10                // float4 segments per row
#define CELLS (CPC*SH*SEGS)    // 480
#define STAGE_FLOATS (CPC*SH*SWP)   // 1920 (7.5 KB)
#define RING 4
#define RING_BYTES (STAGE_FLOATS*4) // 7680

__device__ __forceinline__ uint32_t s2u(const void* p) {
    return (uint32_t)__cvta_generic_to_shared(p);
}

#define CP_ASYNC(sa, gp, sz) \
    asm volatile("cp.async.cg.shared.global [%0], [%1], 16, %2;\n" \
                 :: "r"(sa), "l"(gp), "r"(sz) : "memory")
#define CP_COMMIT() asm volatile("cp.async.commit_group;\n" ::: "memory")
#define CP_WAIT2()  asm volatile("cp.async.wait_group 2;\n" ::: "memory")

__global__ __launch_bounds__(NTHREADS, 7)
void dilate_attn_kernel(const float* __restrict__ q,
                        const float* __restrict__ k,
                        const float* __restrict__ v,
                        float* __restrict__ out)
{
    __shared__ __align__(16) float ring[RING][STAGE_FLOATS];   // 30 KB

    const int tx  = threadIdx.x;              // 0..31
    const int ty  = threadIdx.y;              // 0..3
    const int tid = ty * TW + tx;

    const int tilesX = W_IMG / TW;            // 2
    const int tileX = (blockIdx.x % tilesX) * TW;
    const int tileY = (blockIdx.x / tilesX) * THP;
    const int head  = blockIdx.y;
    const int b     = blockIdx.z;

    // y-pair map: ty {0,1,2,3} -> local rows yA {0,1,4,5}, yB = yA+2
    const int yA = ((ty >> 1) << 2) | (ty & 1);
    const int x  = tileX + tx;
    const int gyA = tileY + yA;

    const float scale = 0.1767766952966369f;  // 32^-0.5

    const size_t base = ((size_t)b * CH + head * HD) * PLANE;
    const float* kb = k + base;
    const float* vb = v + base;
    const float* qbA = q + base + gyA * W_IMG + x;
    const float* qbB = qbA + 2 * W_IMG;

    // ---- precompute staging descriptors (loop-invariant) ----
    // cells: tid, +128, +256, +384 (cell3 valid iff tid < 96 -> warps 0..2)
    int  goff[4], gsz[4];
    uint32_t gsa[4];
    {
        const uint32_t sbase = s2u(&ring[0][0]);
#pragma unroll
        for (int cell = 0; cell < 4; cell++) {
            const int i   = tid + cell * NTHREADS;
            const int ch  = i / (SH * SEGS);
            const int rem = i - ch * (SH * SEGS);
            const int row = rem / SEGS;
            const int seg = rem - row * SEGS;
            const int gy  = tileY - 2 + row;
            const int gx  = tileX - 4 + seg * 4;
            const bool inb = (gy >= 0) & (gy < H_IMG) & (gx >= 0) & (gx < W_IMG);
            goff[cell] = inb ? (ch * PLANE + gy * W_IMG + gx) : 0;
            gsz[cell]  = inb ? 16 : 0;
            gsa[cell]  = sbase + (uint32_t)(ch * (SH * SWP) + row * SWP + seg * 4) * 4u;
        }
    }
    const bool cell3 = (tid < CELLS - 3 * NTHREADS);   // tid < 96

#define ISSUE(srcptr, r) do { \
        CP_ASYNC(gsa[0] + (r) * RING_BYTES, (srcptr) + goff[0], gsz[0]); \
        CP_ASYNC(gsa[1] + (r) * RING_BYTES, (srcptr) + goff[1], gsz[1]); \
        CP_ASYNC(gsa[2] + (r) * RING_BYTES, (srcptr) + goff[2], gsz[2]); \
        if (cell3) CP_ASYNC(gsa[3] + (r) * RING_BYTES, (srcptr) + goff[3], gsz[3]); \
        CP_COMMIT(); \
    } while (0)

    // ---- prologue: issue k stages 0,1,2 ----
    ISSUE(kb,               0);
    ISSUE(kb + 1*CPC*PLANE, 1);
    ISSUE(kb + 2*CPC*PLANE, 2);

    float qcA[CPC], qcB[CPC], qnA[CPC], qnB[CPC];
#pragma unroll
    for (int c = 0; c < CPC; c++) {
        qcA[c] = __ldg(qbA + (size_t)c * PLANE);
        qcB[c] = __ldg(qbB + (size_t)c * PLANE);
    }
#pragma unroll
    for (int c = 0; c < CPC; c++) {
        qnA[c] = __ldg(qbA + (size_t)(CPC + c) * PLANE);
        qnB[c] = __ldg(qbB + (size_t)(CPC + c) * PLANE);
    }

    float lA[KK], lB[KK];
#pragma unroll
    for (int i = 0; i < KK; i++) { lA[i] = 0.f; lB[i] = 0.f; }

    // ================= q.k stages 0..7 =================
#pragma unroll
    for (int s = 0; s < NST_K; s++) {
        CP_WAIT2();
        __syncthreads();

        // issue stage s+3 (k stages 3..7, then v stages 0..2)
        {
            const int sn = s + 3;
            if (sn < NST_K) ISSUE(kb + sn * CPC * PLANE, sn % RING);
            else            ISSUE(vb + (sn - NST_K) * CPC * PLANE, sn % RING);
        }

        // compute stage s: 12 shared tap loads serve 18 FMAs (2 pixels)
        const float* tb = ring[s % RING];
#pragma unroll
        for (int c = 0; c < CPC; c++) {
            // smem rows yA+2r (r=0..3) = image rows gyA-2, gyA, gyA+2, gyA+4
            // col base tx+2: image x-2 (kj=0 tap); smem col of gx is localx+4
            const float* tc = tb + c * (SH * SWP) + yA * SWP + tx + 2;
            float tap[4][3];
#pragma unroll
            for (int r = 0; r < 4; r++)
#pragma unroll
                for (int j = 0; j < 3; j++)
                    tap[r][j] = tc[(2 * r) * SWP + 2 * j];
            const float qA = qcA[c], qB = qcB[c];
#pragma unroll
            for (int r = 0; r < 3; r++)
#pragma unroll
                for (int j = 0; j < 3; j++) {
                    lA[r * 3 + j] = fmaf(qA, tap[r][j],     lA[r * 3 + j]);
                    lB[r * 3 + j] = fmaf(qB, tap[r + 1][j], lB[r * 3 + j]);
                }
        }

        // rotate q prefetch (distance 2)
#pragma unroll
        for (int c = 0; c < CPC; c++) { qcA[c] = qnA[c]; qcB[c] = qnB[c]; }
        if (s + 2 < NST_K) {
#pragma unroll
            for (int c = 0; c < CPC; c++) {
                qnA[c] = __ldg(qbA + (size_t)((s + 2) * CPC + c) * PLANE);
                qnB[c] = __ldg(qbB + (size_t)((s + 2) * CPC + c) * PLANE);
            }
        }
    }

    // ================= softmax over 9 taps (both pixels) =================
    {
        float mA = -1e30f, mB = -1e30f;
#pragma unroll
        for (int i = 0; i < KK; i++) {
            lA[i] *= scale; lB[i] *= scale;
            mA = fmaxf(mA, lA[i]); mB = fmaxf(mB, lB[i]);
        }
        float sA = 0.f, sB = 0.f;
#pragma unroll
        for (int i = 0; i < KK; i++) {
            lA[i] = __expf(lA[i] - mA); sA += lA[i];
            lB[i] = __expf(lB[i] - mB); sB += lB[i];
        }
        const float iA = 1.f / sA, iB = 1.f / sB;
#pragma unroll
        for (int i = 0; i < KK; i++) { lA[i] *= iA; lB[i] *= iB; }  // weights
    }

    // ================= a.v stages 8..15 =================
    float* opA = out + ((size_t)b * PLANE + gyA * W_IMG + x) * CH + head * HD;
    float* opB = opA + 2 * W_IMG * CH;

#pragma unroll
    for (int s = NST_K; s < NST; s++) {
        CP_WAIT2();
        __syncthreads();

        {
            const int sn = s + 3;
            if (sn < NST) ISSUE(vb + (sn - NST_K) * CPC * PLANE, sn % RING);
            else          CP_COMMIT();   // empty group keeps drain count ahead
        }

        const float* tb = ring[s % RING];
        float oA[CPC], oB[CPC];
#pragma unroll
        for (int c = 0; c < CPC; c++) {
            const float* tc = tb + c * (SH * SWP) + yA * SWP + tx + 2;
            float tap[4][3];
#pragma unroll
            for (int r = 0; r < 4; r++)
#pragma unroll
                for (int j = 0; j < 3; j++)
                    tap[r][j] = tc[(2 * r) * SWP + 2 * j];
            float aA = 0.f, aB = 0.f;
#pragma unroll
            for (int r = 0; r < 3; r++)
#pragma unroll
                for (int j = 0; j < 3; j++) {
                    aA = fmaf(lA[r * 3 + j], tap[r][j],     aA);
                    aB = fmaf(lB[r * 3 + j], tap[r + 1][j], aB);
                }
            oA[c] = aA; oB[c] = aB;
        }

        const int c0 = (s - NST_K) * CPC;
        *reinterpret_cast<float4*>(opA + c0) = make_float4(oA[0], oA[1], oA[2], oA[3]);
        *reinterpret_cast<float4*>(opB + c0) = make_float4(oB[0], oB[1], oB[2], oB[3]);
    }
#undef ISSUE
}

extern "C" void kernel_launch(void* const* d_in, const int* in_sizes, int n_in,
                              void* d_out, int out_size)
{
    const float* q = (const float*)d_in[0];
    const float* k = (const float*)d_in[1];
    const float* v = (const float*)d_in[2];
    float* out = (float*)d_out;

    dim3 block(TW, TYD);
    dim3 grid((W_IMG / TW) * (H_IMG / THP), HEADS, 16 /*B*/);
    dilate_attn_kernel<<<grid, block>>>(q, k, v, out);
}

// round 15
// speedup vs baseline: 1.1966x; 1.0528x over previous
#include <cuda_runtime.h>
#include <cstdint>

#define H_IMG 64
#define W_IMG 64
#define CH    128
#define HD    32
#define HEADS 4
#define KS    3
#define DIL   2
#define KK    9
#define PLANE 4096

#define TW 32                  // tile width (pixels)
#define THP 8                  // tile height (pixels)
#define TYD 4                  // thread rows (2 px/thread, y-stride-2 pairs)
#define HALVES 2               // channel split
#define NTHREADS (TW*TYD*HALVES)   // 256

#define CPC 8                  // channels staged per stage (4 per half)
#define NST_K 4                // k stages
#define NST   8                // total stages
#define SH (THP + 4)           // 12 smem rows
#define SWP 40                 // padded cols
#define SEGS 10
#define CELLS (CPC*SH*SEGS)    // 960
#define STAGE_FLOATS (CPC*SH*SWP)   // 3840 (15.36 KB)
#define RING 3
#define RING_BYTES (STAGE_FLOATS*4) // 15360

__device__ __forceinline__ uint32_t s2u(const void* p) {
    return (uint32_t)__cvta_generic_to_shared(p);
}

#define CP_ASYNC(sa, gp, sz) \
    asm volatile("cp.async.cg.shared.global [%0], [%1], 16, %2;\n" \
                 :: "r"(sa), "l"(gp), "r"(sz) : "memory")
#define CP_COMMIT() asm volatile("cp.async.commit_group;\n" ::: "memory")
#define CP_WAIT1()  asm volatile("cp.async.wait_group 1;\n" ::: "memory")

__global__ __launch_bounds__(NTHREADS, 4)
void dilate_attn_kernel(const float* __restrict__ q,
                        const float* __restrict__ k,
                        const float* __restrict__ v,
                        float* __restrict__ out)
{
    __shared__ __align__(16) float ring[RING][STAGE_FLOATS];   // 46.1 KB

    const int tx = threadIdx.x;               // 0..31
    const int ty = threadIdx.y;               // 0..3
    const int h  = threadIdx.z;               // 0..1 channel half
    const int tid = (h * TYD + ty) * TW + tx; // partner = tid ^ 128

    const int tilesX = W_IMG / TW;            // 2
    const int tileX = (blockIdx.x % tilesX) * TW;
    const int tileY = (blockIdx.x / tilesX) * THP;
    const int head  = blockIdx.y;
    const int b     = blockIdx.z;

    // y-pair map: ty {0,1,2,3} -> local rows yA {0,1,4,5}, yB = yA+2
    const int yA = ((ty >> 1) << 2) | (ty & 1);
    const int x  = tileX + tx;
    const int gyA = tileY + yA;

    const float scale = 0.1767766952966369f;  // 32^-0.5

    const size_t base = ((size_t)b * CH + head * HD) * PLANE;
    const float* kb = k + base;
    const float* vb = v + base;
    const float* qbA = q + base + gyA * W_IMG + x;
    const float* qbB = qbA + 2 * W_IMG;

    // ---- precompute staging descriptors (loop-invariant) ----
    // cells: tid, +256, +512, +768 (cell3 valid iff tid < 192 -> warps 0..5)
    int  goff[4], gsz[4];
    uint32_t gsa[4];
    {
        const uint32_t sbase = s2u(&ring[0][0]);
#pragma unroll
        for (int cell = 0; cell < 4; cell++) {
            const int i   = tid + cell * NTHREADS;
            const int ch  = i / (SH * SEGS);
            const int rem = i - ch * (SH * SEGS);
            const int row = rem / SEGS;
            const int seg = rem - row * SEGS;
            const int gy  = tileY - 2 + row;
            const int gx  = tileX - 4 + seg * 4;
            const bool inb = (gy >= 0) & (gy < H_IMG) & (gx >= 0) & (gx < W_IMG);
            goff[cell] = inb ? (ch * PLANE + gy * W_IMG + gx) : 0;
            gsz[cell]  = inb ? 16 : 0;
            gsa[cell]  = sbase + (uint32_t)(ch * (SH * SWP) + row * SWP + seg * 4) * 4u;
        }
    }
    const bool cell3 = (tid < CELLS - 3 * NTHREADS);   // tid < 192

#define ISSUE(srcptr, r) do { \
        CP_ASYNC(gsa[0] + (r) * RING_BYTES, (srcptr) + goff[0], gsz[0]); \
        CP_ASYNC(gsa[1] + (r) * RING_BYTES, (srcptr) + goff[1], gsz[1]); \
        CP_ASYNC(gsa[2] + (r) * RING_BYTES, (srcptr) + goff[2], gsz[2]); \
        if (cell3) CP_ASYNC(gsa[3] + (r) * RING_BYTES, (srcptr) + goff[3], gsz[3]); \
        CP_COMMIT(); \
    } while (0)

    // ---- prologue: issue k stages 0,1 ----
    ISSUE(kb,             0);
    ISSUE(kb + CPC*PLANE, 1);

    // q for this thread's half: stage s channels s*8 + h*4 + c
    const int hoff = h * 4;
    float qcA[4], qcB[4], qnA[4], qnB[4];
#pragma unroll
    for (int c = 0; c < 4; c++) {
        qcA[c] = __ldg(qbA + (size_t)(hoff + c) * PLANE);
        qcB[c] = __ldg(qbB + (size_t)(hoff + c) * PLANE);
        qnA[c] = __ldg(qbA + (size_t)(CPC + hoff + c) * PLANE);
        qnB[c] = __ldg(qbB + (size_t)(CPC + hoff + c) * PLANE);
    }

    float lA[KK], lB[KK];
#pragma unroll
    for (int i = 0; i < KK; i++) { lA[i] = 0.f; lB[i] = 0.f; }

    // ================= q.k stages 0..3 (16 channels per half) =================
#pragma unroll
    for (int s = 0; s < NST_K; s++) {
        CP_WAIT1();
        __syncthreads();

        {   // issue stage s+2 (k stages 2,3 then v stages 0,1)
            const int sn = s + 2;
            if (sn < NST_K) ISSUE(kb + sn * CPC * PLANE, sn % RING);
            else            ISSUE(vb + (sn - NST_K) * CPC * PLANE, sn % RING);
        }

        const float* tb = ring[s % RING];
#pragma unroll
        for (int c = 0; c < 4; c++) {
            const float* tc = tb + (hoff + c) * (SH * SWP) + yA * SWP + tx + 2;
            float tap[4][3];
#pragma unroll
            for (int r = 0; r < 4; r++)
#pragma unroll
                for (int j = 0; j < 3; j++)
                    tap[r][j] = tc[(2 * r) * SWP + 2 * j];
            const float qA = qcA[c], qB = qcB[c];
#pragma unroll
            for (int r = 0; r < 3; r++)
#pragma unroll
                for (int j = 0; j < 3; j++) {
                    lA[r * 3 + j] = fmaf(qA, tap[r][j],     lA[r * 3 + j]);
                    lB[r * 3 + j] = fmaf(qB, tap[r + 1][j], lB[r * 3 + j]);
                }
        }

        // rotate q prefetch (distance 2 stages)
#pragma unroll
        for (int c = 0; c < 4; c++) { qcA[c] = qnA[c]; qcB[c] = qnB[c]; }
        if (s + 2 < NST_K) {
#pragma unroll
            for (int c = 0; c < 4; c++) {
                qnA[c] = __ldg(qbA + (size_t)((s + 2) * CPC + hoff + c) * PLANE);
                qnB[c] = __ldg(qbB + (size_t)((s + 2) * CPC + hoff + c) * PLANE);
            }
        }
    }

    // ================= cross-half logit exchange (ring slot 0 is free) ========
    // slot usage now: stage 4 -> slot 1, stage 5 -> slot 2 (in flight); slot 0 idle
    __syncthreads();                       // all tap reads of slot 0 done
    {
        float* xch = &ring[0][0];          // 256*9 floats = 9.2 KB
        const int own = tid * KK;
        const int par = (tid ^ 128) * KK;  // stride 9: conflict-free
#pragma unroll
        for (int i = 0; i < KK; i++) xch[own + i] = lA[i];
        __syncthreads();
#pragma unroll
        for (int i = 0; i < KK; i++) lA[i] += xch[par + i];
        __syncthreads();
#pragma unroll
        for (int i = 0; i < KK; i++) xch[own + i] = lB[i];
        __syncthreads();
#pragma unroll
        for (int i = 0; i < KK; i++) lB[i] += xch[par + i];
        // v-loop top __syncthreads orders these reads before slot-0 reuse
    }

    // ================= softmax (computed redundantly in both halves) ==========
    {
        float mA = -1e30f, mB = -1e30f;
#pragma unroll
        for (int i = 0; i < KK; i++) {
            lA[i] *= scale; lB[i] *= scale;
            mA = fmaxf(mA, lA[i]); mB = fmaxf(mB, lB[i]);
        }
        float sA = 0.f, sB = 0.f;
#pragma unroll
        for (int i = 0; i < KK; i++) {
            lA[i] = __expf(lA[i] - mA); sA += lA[i];
            lB[i] = __expf(lB[i] - mB); sB += lB[i];
        }
        const float iA = 1.f / sA, iB = 1.f / sB;
#pragma unroll
        for (int i = 0; i < KK; i++) { lA[i] *= iA; lB[i] *= iB; }  // weights
    }

    // ================= a.v stages 4..7 =================
    float* opA = out + ((size_t)b * PLANE + gyA * W_IMG + x) * CH + head * HD;
    float* opB = opA + 2 * W_IMG * CH;

#pragma unroll
    for (int s = NST_K; s < NST; s++) {
        CP_WAIT1();
        __syncthreads();

        {
            const int sn = s + 2;
            if (sn < NST) ISSUE(vb + (sn - NST_K) * CPC * PLANE, sn % RING);
            else          CP_COMMIT();   // empty group keeps drain count ahead
        }

        const float* tb = ring[s % RING];
        float oA[4], oB[4];
#pragma unroll
        for (int c = 0; c < 4; c++) {
            const float* tc = tb + (hoff + c) * (SH * SWP) + yA * SWP + tx + 2;
            float tap[4][3];
#pragma unroll
            for (int r = 0; r < 4; r++)
#pragma unroll
                for (int j = 0; j < 3; j++)
                    tap[r][j] = tc[(2 * r) * SWP + 2 * j];
            float aA = 0.f, aB = 0.f;
#pragma unroll
            for (int r = 0; r < 3; r++)
#pragma unroll
                for (int j = 0; j < 3; j++) {
                    aA = fmaf(lA[r * 3 + j], tap[r][j],     aA);
                    aB = fmaf(lB[r * 3 + j], tap[r + 1][j], aB);
                }
            oA[c] = aA; oB[c] = aB;
        }

        const int c0 = (s - NST_K) * CPC + hoff;
        *reinterpret_cast<float4*>(opA + c0) = make_float4(oA[0], oA[1], oA[2], oA[3]);
        *reinterpret_cast<float4*>(opB + c0) = make_float4(oB[0], oB[1], oB[2], oB[3]);
    }
#undef ISSUE
}

extern "C" void kernel_launch(void* const* d_in, const int* in_sizes, int n_in,
                              void* d_out, int out_size)
{
    const float* q = (const float*)d_in[0];
    const float* k = (const float*)d_in[1];
    const float* v = (const float*)d_in[2];
    float* out = (float*)d_out;

    dim3 block(TW, TYD, HALVES);
    dim3 grid((W_IMG / TW) * (H_IMG / THP), HEADS, 16 /*B*/);
    dilate_attn_kernel<<<grid, block>>>(q, k, v, out);
}